// round 1
// baseline (speedup 1.0000x reference)
#include <cuda_runtime.h>
#include <cuda_fp16.h>
#include <cstdint>

#define BATCH 1024
#define CIN   512
#define HW    49
#define KDIM  2304          // 9 * 256
#define MDIM  50176         // 1024 * 49
#define NDIM  512

// Scratch (allocated at module load; no runtime allocation)
__device__ __half Acol_g[(size_t)MDIM * KDIM];   // 231 MB im2col, fp16
__device__ __half Wh_g[(size_t)KDIM * NDIM];     // permuted weights, fp16

// ---------------------------------------------------------------------------
// Phase 1a: build im2col matrix A[m=(b,n,p)][kk=(j*3+k)*256+l] in fp16.
//   valid iff 1 <= p+k <= 7;  w2 = (p+k-2) mod 7
//   val = xz[b,256+l, ((n-1)%7)+j-1, w2] + xz[b,l, n+j-1, w2]
// One block per batch; x[b] staged in shared memory (512*49 floats).
// ---------------------------------------------------------------------------
__global__ void prep_a(const float* __restrict__ x) {
    extern __shared__ float xs[];  // 512*49 floats = 100352 B
    const int b = blockIdx.x;
    const float4* src = (const float4*)(x + (size_t)b * CIN * HW);
    float4* dst = (float4*)xs;
    for (int i = threadIdx.x; i < CIN * HW / 4; i += blockDim.x) dst[i] = src[i];
    __syncthreads();

    __half2* aout = (__half2*)(Acol_g + (size_t)b * HW * KDIM);
    const int total2 = HW * KDIM / 2;  // 56448 half2 per batch
    for (int idx = threadIdx.x; idx < total2; idx += blockDim.x) {
        int np = idx / 1152;           // 1152 = 2304/2
        int r  = idx - np * 1152;
        int jk = r >> 7;               // 0..8
        int l2 = r & 127;
        int l  = l2 * 2;
        int j  = jk / 3, k = jk - j * 3;
        int n  = np / 7, p = np - n * 7;

        float v0 = 0.f, v1 = 0.f;
        int pk = p + k;
        if (pk >= 1 && pk <= 7) {
            int w2 = (pk + 5) % 7;
            int ha = ((n + 6) % 7) + j - 1;   // group-1 channel row
            int hb = n + j - 1;               // group-0 channel row
            if (ha >= 0 && ha < 7) {
                v0 += xs[(256 + l) * HW + ha * 7 + w2];
                v1 += xs[(257 + l) * HW + ha * 7 + w2];
            }
            if (hb >= 0 && hb < 7) {
                v0 += xs[l * HW + hb * 7 + w2];
                v1 += xs[(l + 1) * HW + hb * 7 + w2];
            }
        }
        aout[idx] = __floats2half2_rn(v0, v1);
    }
}

// ---------------------------------------------------------------------------
// Phase 1b: Wh[kk=(j*3+k)*256+l][i] = fp16( W[l][j][k][i] )
// ---------------------------------------------------------------------------
__global__ void prep_w(const float* __restrict__ W) {
    int t = blockIdx.x * blockDim.x + threadIdx.x;  // over 2304*256 half2
    if (t >= KDIM * (NDIM / 2)) return;
    int kk = t >> 8;            // /256
    int i2 = t & 255;
    int l  = kk & 255;
    int jk = kk >> 8;
    float2 v = ((const float2*)W)[(size_t)(l * 9 + jk) * 256 + i2];
    ((__half2*)Wh_g)[t] = __floats2half2_rn(v.x, v.y);
}

// ---------------------------------------------------------------------------
// Phase 2: GEMM  out[m][i] = sum_k A[m][k] * Wh[k][i]
// 128x128x32 tiles, double-buffered cp.async, ldmatrix + mma.sync f16->f32.
// 8 warps (2x4); each warp 64x32. Exact tiling: grid (4, 392).
// Epilogue scatters to out[b, i, n, p] = out[(b*512+i)*49 + n*7+p].
// ---------------------------------------------------------------------------
#define BM 128
#define BN 128
#define BK 32
#define APAD 40    // halfs per A row (32 + 8 pad)
#define BPAD 136   // halfs per B row (128 + 8 pad)

__device__ __forceinline__ void load_stage(
    const __half* __restrict__ Ag, const __half* __restrict__ Bg,
    __half* As, __half* Bs, int k0, int tid)
{
    // A: 128 rows x 32 halfs = 512 x 16B chunks; 2 per thread
    {
        int row = tid >> 1;
        int cb  = (tid & 1) * 2;
#pragma unroll
        for (int q = 0; q < 2; q++) {
            int c = cb + q;
            uint32_t s = (uint32_t)__cvta_generic_to_shared(&As[row * APAD + c * 8]);
            const __half* g = Ag + (size_t)row * KDIM + k0 + c * 8;
            asm volatile("cp.async.cg.shared.global [%0], [%1], 16;\n" :: "r"(s), "l"(g));
        }
    }
    // B: 32 rows x 128 halfs = 512 x 16B chunks; 2 per thread
    {
        int row = tid >> 3;
        int cb  = (tid & 7) * 2;
#pragma unroll
        for (int q = 0; q < 2; q++) {
            int c = cb + q;
            uint32_t s = (uint32_t)__cvta_generic_to_shared(&Bs[row * BPAD + c * 8]);
            const __half* g = Bg + (size_t)(k0 + row) * NDIM + c * 8;
            asm volatile("cp.async.cg.shared.global [%0], [%1], 16;\n" :: "r"(s), "l"(g));
        }
    }
    asm volatile("cp.async.commit_group;\n");
}

__global__ __launch_bounds__(256, 2) void gemm_f16(float* __restrict__ out) {
    __shared__ __half As[2][BM * APAD];
    __shared__ __half Bs[2][BK * BPAD];

    const int bn   = blockIdx.x;     // 0..3
    const int bm   = blockIdx.y;     // 0..391
    const int tid  = threadIdx.x;
    const int wid  = tid >> 5;
    const int lane = tid & 31;
    const int wm   = wid >> 2;       // 0..1
    const int wn   = wid & 3;        // 0..3

    const __half* Ag = Acol_g + (size_t)bm * BM * KDIM;
    const __half* Bg = Wh_g + bn * BN;

    float acc[4][4][4];
#pragma unroll
    for (int a = 0; a < 4; a++)
#pragma unroll
        for (int b = 0; b < 4; b++)
#pragma unroll
            for (int c = 0; c < 4; c++) acc[a][b][c] = 0.f;

    load_stage(Ag, Bg, As[0], Bs[0], 0, tid);

    const int NSTAGE = KDIM / BK;  // 72
    for (int t = 0; t < NSTAGE; t++) {
        if (t + 1 < NSTAGE) {
            load_stage(Ag, Bg, As[(t + 1) & 1], Bs[(t + 1) & 1], (t + 1) * BK, tid);
            asm volatile("cp.async.wait_group 1;\n");
        } else {
            asm volatile("cp.async.wait_group 0;\n");
        }
        __syncthreads();

        const __half* Asb = As[t & 1];
        const __half* Bsb = Bs[t & 1];
#pragma unroll
        for (int ks = 0; ks < 2; ks++) {
            const int kb = ks * 16;
            uint32_t a[4][4];
#pragma unroll
            for (int mi = 0; mi < 4; mi++) {
                int r = wm * 64 + mi * 16 + (lane & 15);
                int c = kb + (lane >> 4) * 8;
                uint32_t s = (uint32_t)__cvta_generic_to_shared(&Asb[r * APAD + c]);
                asm volatile("ldmatrix.sync.aligned.m8n8.x4.shared.b16 {%0,%1,%2,%3}, [%4];\n"
                             : "=r"(a[mi][0]), "=r"(a[mi][1]), "=r"(a[mi][2]), "=r"(a[mi][3])
                             : "r"(s));
            }
            uint32_t bf[4][2];
#pragma unroll
            for (int ni = 0; ni < 4; ni++) {
                int r = kb + (lane & 15);
                int c = wn * 32 + ni * 8;
                uint32_t s = (uint32_t)__cvta_generic_to_shared(&Bsb[r * BPAD + c]);
                asm volatile("ldmatrix.sync.aligned.m8n8.x2.trans.shared.b16 {%0,%1}, [%2];\n"
                             : "=r"(bf[ni][0]), "=r"(bf[ni][1])
                             : "r"(s));
            }
#pragma unroll
            for (int mi = 0; mi < 4; mi++)
#pragma unroll
                for (int ni = 0; ni < 4; ni++) {
                    asm volatile(
                        "mma.sync.aligned.m16n8k16.row.col.f32.f16.f16.f32 "
                        "{%0,%1,%2,%3}, {%4,%5,%6,%7}, {%8,%9}, {%0,%1,%2,%3};\n"
                        : "+f"(acc[mi][ni][0]), "+f"(acc[mi][ni][1]),
                          "+f"(acc[mi][ni][2]), "+f"(acc[mi][ni][3])
                        : "r"(a[mi][0]), "r"(a[mi][1]), "r"(a[mi][2]), "r"(a[mi][3]),
                          "r"(bf[ni][0]), "r"(bf[ni][1]));
                }
        }
        __syncthreads();
    }

    // Epilogue: scatter to out[(b*512 + i)*49 + np]
    const int m_base = bm * BM + wm * 64;
    const int i_base = bn * BN + wn * 32;
#pragma unroll
    for (int mi = 0; mi < 4; mi++) {
#pragma unroll
        for (int ni = 0; ni < 4; ni++) {
            int row0 = m_base + mi * 16 + (lane >> 2);
            int col0 = i_base + ni * 8 + (lane & 3) * 2;
#pragma unroll
            for (int h = 0; h < 2; h++) {
                int m  = row0 + h * 8;
                int b  = m / 49;
                int np = m - b * 49;
                float* o = out + (size_t)(b * NDIM + col0) * 49 + np;
                o[0]  = acc[mi][ni][h * 2 + 0];
                o[49] = acc[mi][ni][h * 2 + 1];
            }
        }
    }
}

// ---------------------------------------------------------------------------
extern "C" void kernel_launch(void* const* d_in, const int* in_sizes, int n_in,
                              void* d_out, int out_size) {
    const float* x = (const float*)d_in[0];   // (1024, 512, 7, 7)
    const float* W = (const float*)d_in[1];   // (256, 3, 3, 512)
    float* out = (float*)d_out;               // (1024, 512, 7, 7)

    cudaFuncSetAttribute(prep_a, cudaFuncAttributeMaxDynamicSharedMemorySize,
                         CIN * HW * (int)sizeof(float));

    prep_a<<<BATCH, 256, CIN * HW * sizeof(float)>>>(x);
    prep_w<<<(KDIM * (NDIM / 2) + 255) / 256, 256>>>(W);
    gemm_f16<<<dim3(NDIM / BN, MDIM / BM), 256>>>(out);
}

// round 2
// speedup vs baseline: 1.0002x; 1.0002x over previous
#include <cuda_runtime.h>
#include <cuda_fp16.h>
#include <cstdint>

#define BATCH 1024
#define CIN   512
#define HW    49
#define KDIM  2304          // 9 * 256
#define MDIM  50176         // 1024 * 49
#define NDIM  512

// Scratch (allocated at module load; no runtime allocation)
__device__ __half Acol_g[(size_t)MDIM * KDIM];   // 231 MB im2col, fp16
__device__ __half Wh_g[(size_t)KDIM * NDIM];     // permuted weights, fp16

// ---------------------------------------------------------------------------
// Phase 1a: build im2col matrix A[m=(b,n,p)][kk=(j*3+k)*256+l] in fp16.
//   valid iff 1 <= p+k <= 7;  w2 = (p+k-2) mod 7
//   val = xz[b,256+l, ((n-1)%7)+j-1, w2] + xz[b,l, n+j-1, w2]
// One block per batch; x[b] staged in shared memory (512*49 floats).
// ---------------------------------------------------------------------------
__global__ void prep_a(const float* __restrict__ x) {
    extern __shared__ float xs[];  // 512*49 floats = 100352 B
    const int b = blockIdx.x;
    const float4* src = (const float4*)(x + (size_t)b * CIN * HW);
    float4* dst = (float4*)xs;
    for (int i = threadIdx.x; i < CIN * HW / 4; i += blockDim.x) dst[i] = src[i];
    __syncthreads();

    __half2* aout = (__half2*)(Acol_g + (size_t)b * HW * KDIM);
    const int total2 = HW * KDIM / 2;  // 56448 half2 per batch
    for (int idx = threadIdx.x; idx < total2; idx += blockDim.x) {
        int np = idx / 1152;           // 1152 = 2304/2
        int r  = idx - np * 1152;
        int jk = r >> 7;               // 0..8
        int l2 = r & 127;
        int l  = l2 * 2;
        int j  = jk / 3, k = jk - j * 3;
        int n  = np / 7, p = np - n * 7;

        float v0 = 0.f, v1 = 0.f;
        int pk = p + k;
        if (pk >= 1 && pk <= 7) {
            int w2 = (pk + 5) % 7;
            int ha = ((n + 6) % 7) + j - 1;   // group-1 channel row
            int hb = n + j - 1;               // group-0 channel row
            if (ha >= 0 && ha < 7) {
                v0 += xs[(256 + l) * HW + ha * 7 + w2];
                v1 += xs[(257 + l) * HW + ha * 7 + w2];
            }
            if (hb >= 0 && hb < 7) {
                v0 += xs[l * HW + hb * 7 + w2];
                v1 += xs[(l + 1) * HW + hb * 7 + w2];
            }
        }
        aout[idx] = __floats2half2_rn(v0, v1);
    }
}

// ---------------------------------------------------------------------------
// Phase 1b: Wh[kk=(j*3+k)*256+l][i] = fp16( W[l][j][k][i] )
// ---------------------------------------------------------------------------
__global__ void prep_w(const float* __restrict__ W) {
    int t = blockIdx.x * blockDim.x + threadIdx.x;  // over 2304*256 half2
    if (t >= KDIM * (NDIM / 2)) return;
    int kk = t >> 8;            // /256
    int i2 = t & 255;
    int l  = kk & 255;
    int jk = kk >> 8;
    float2 v = ((const float2*)W)[(size_t)(l * 9 + jk) * 256 + i2];
    ((__half2*)Wh_g)[t] = __floats2half2_rn(v.x, v.y);
}

// ---------------------------------------------------------------------------
// Phase 2: GEMM  out[m][i] = sum_k A[m][k] * Wh[k][i]
// 128x128x32 tiles, double-buffered cp.async, ldmatrix + mma.sync f16->f32.
// 8 warps (2x4); each warp 64x32. Exact tiling: grid (4, 392).
// Epilogue scatters to out[b, i, n, p] = out[(b*512+i)*49 + n*7+p].
// ---------------------------------------------------------------------------
#define BM 128
#define BN 128
#define BK 32
#define APAD 40    // halfs per A row (32 + 8 pad)
#define BPAD 136   // halfs per B row (128 + 8 pad)

__device__ __forceinline__ void load_stage(
    const __half* __restrict__ Ag, const __half* __restrict__ Bg,
    __half* As, __half* Bs, int k0, int tid)
{
    // A: 128 rows x 32 halfs = 512 x 16B chunks; 2 per thread
    {
        int row = tid >> 1;
        int cb  = (tid & 1) * 2;
#pragma unroll
        for (int q = 0; q < 2; q++) {
            int c = cb + q;
            uint32_t s = (uint32_t)__cvta_generic_to_shared(&As[row * APAD + c * 8]);
            const __half* g = Ag + (size_t)row * KDIM + k0 + c * 8;
            asm volatile("cp.async.cg.shared.global [%0], [%1], 16;\n" :: "r"(s), "l"(g));
        }
    }
    // B: 32 rows x 128 halfs = 512 x 16B chunks; 2 per thread
    {
        int row = tid >> 3;
        int cb  = (tid & 7) * 2;
#pragma unroll
        for (int q = 0; q < 2; q++) {
            int c = cb + q;
            uint32_t s = (uint32_t)__cvta_generic_to_shared(&Bs[row * BPAD + c * 8]);
            const __half* g = Bg + (size_t)(k0 + row) * NDIM + c * 8;
            asm volatile("cp.async.cg.shared.global [%0], [%1], 16;\n" :: "r"(s), "l"(g));
        }
    }
    asm volatile("cp.async.commit_group;\n");
}

__global__ __launch_bounds__(256, 2) void gemm_f16(float* __restrict__ out) {
    __shared__ __half As[2][BM * APAD];
    __shared__ __half Bs[2][BK * BPAD];

    const int bn   = blockIdx.x;     // 0..3
    const int bm   = blockIdx.y;     // 0..391
    const int tid  = threadIdx.x;
    const int wid  = tid >> 5;
    const int lane = tid & 31;
    const int wm   = wid >> 2;       // 0..1
    const int wn   = wid & 3;        // 0..3

    const __half* Ag = Acol_g + (size_t)bm * BM * KDIM;
    const __half* Bg = Wh_g + bn * BN;

    float acc[4][4][4];
#pragma unroll
    for (int a = 0; a < 4; a++)
#pragma unroll
        for (int b = 0; b < 4; b++)
#pragma unroll
            for (int c = 0; c < 4; c++) acc[a][b][c] = 0.f;

    load_stage(Ag, Bg, As[0], Bs[0], 0, tid);

    const int NSTAGE = KDIM / BK;  // 72
    for (int t = 0; t < NSTAGE; t++) {
        if (t + 1 < NSTAGE) {
            load_stage(Ag, Bg, As[(t + 1) & 1], Bs[(t + 1) & 1], (t + 1) * BK, tid);
            asm volatile("cp.async.wait_group 1;\n");
        } else {
            asm volatile("cp.async.wait_group 0;\n");
        }
        __syncthreads();

        const __half* Asb = As[t & 1];
        const __half* Bsb = Bs[t & 1];
#pragma unroll
        for (int ks = 0; ks < 2; ks++) {
            const int kb = ks * 16;
            uint32_t a[4][4];
#pragma unroll
            for (int mi = 0; mi < 4; mi++) {
                int r = wm * 64 + mi * 16 + (lane & 15);
                int c = kb + (lane >> 4) * 8;
                uint32_t s = (uint32_t)__cvta_generic_to_shared(&Asb[r * APAD + c]);
                asm volatile("ldmatrix.sync.aligned.m8n8.x4.shared.b16 {%0,%1,%2,%3}, [%4];\n"
                             : "=r"(a[mi][0]), "=r"(a[mi][1]), "=r"(a[mi][2]), "=r"(a[mi][3])
                             : "r"(s));
            }
            uint32_t bf[4][2];
#pragma unroll
            for (int ni = 0; ni < 4; ni++) {
                int r = kb + (lane & 15);
                int c = wn * 32 + ni * 8;
                uint32_t s = (uint32_t)__cvta_generic_to_shared(&Bsb[r * BPAD + c]);
                asm volatile("ldmatrix.sync.aligned.m8n8.x2.trans.shared.b16 {%0,%1}, [%2];\n"
                             : "=r"(bf[ni][0]), "=r"(bf[ni][1])
                             : "r"(s));
            }
#pragma unroll
            for (int mi = 0; mi < 4; mi++)
#pragma unroll
                for (int ni = 0; ni < 4; ni++) {
                    asm volatile(
                        "mma.sync.aligned.m16n8k16.row.col.f32.f16.f16.f32 "
                        "{%0,%1,%2,%3}, {%4,%5,%6,%7}, {%8,%9}, {%0,%1,%2,%3};\n"
                        : "+f"(acc[mi][ni][0]), "+f"(acc[mi][ni][1]),
                          "+f"(acc[mi][ni][2]), "+f"(acc[mi][ni][3])
                        : "r"(a[mi][0]), "r"(a[mi][1]), "r"(a[mi][2]), "r"(a[mi][3]),
                          "r"(bf[ni][0]), "r"(bf[ni][1]));
                }
        }
        __syncthreads();
    }

    // Epilogue: scatter to out[(b*512 + i)*49 + np]
    const int m_base = bm * BM + wm * 64;
    const int i_base = bn * BN + wn * 32;
#pragma unroll
    for (int mi = 0; mi < 4; mi++) {
#pragma unroll
        for (int ni = 0; ni < 4; ni++) {
            int row0 = m_base + mi * 16 + (lane >> 2);
            int col0 = i_base + ni * 8 + (lane & 3) * 2;
#pragma unroll
            for (int h = 0; h < 2; h++) {
                int m  = row0 + h * 8;
                int b  = m / 49;
                int np = m - b * 49;
                float* o = out + (size_t)(b * NDIM + col0) * 49 + np;
                o[0]  = acc[mi][ni][h * 2 + 0];
                o[49] = acc[mi][ni][h * 2 + 1];
            }
        }
    }
}

// ---------------------------------------------------------------------------
extern "C" void kernel_launch(void* const* d_in, const int* in_sizes, int n_in,
                              void* d_out, int out_size) {
    const float* x = (const float*)d_in[0];   // (1024, 512, 7, 7)
    const float* W = (const float*)d_in[1];   // (256, 3, 3, 512)
    float* out = (float*)d_out;               // (1024, 512, 7, 7)

    cudaFuncSetAttribute(prep_a, cudaFuncAttributeMaxDynamicSharedMemorySize,
                         CIN * HW * (int)sizeof(float));

    prep_a<<<BATCH, 256, CIN * HW * sizeof(float)>>>(x);
    prep_w<<<(KDIM * (NDIM / 2) + 255) / 256, 256>>>(W);
    gemm_f16<<<dim3(NDIM / BN, MDIM / BM), 256>>>(out);
}

// round 4
// speedup vs baseline: 1.4285x; 1.4283x over previous
#include <cuda_runtime.h>
#include <cuda_fp16.h>
#include <cstdint>

#define BATCH 1024
#define CIN   512
#define HW    49
#define KDIM  2304          // 9 * 256
#define MDIM  50176         // 1024 * 49
#define NDIM  512

// Scratch (module-load allocation; legal per harness rules)
__device__ __align__(16) __half Acol_g[(size_t)MDIM * KDIM];   // [m][kk]   231 MB
__device__ __align__(16) __half Whn_g[(size_t)NDIM * KDIM];    // [i][kk]   2.3 MB (K-major)

// ---------------------------------------------------------------------------
// helpers
// ---------------------------------------------------------------------------
__device__ __forceinline__ uint32_t s2u(const void* p) {
    uint32_t a;
    asm("{ .reg .u64 t; cvta.to.shared.u64 t, %1; cvt.u32.u64 %0, t; }" : "=r"(a) : "l"(p));
    return a;
}
__device__ __forceinline__ uint32_t swz(uint32_t o) { return o ^ ((o >> 3) & 0x70); }

__device__ __forceinline__ void cpa16(uint32_t s, const void* g) {
    asm volatile("cp.async.cg.shared.global [%0], [%1], 16;" :: "r"(s), "l"(g));
}

// ---------------------------------------------------------------------------
// Phase 1a: im2col A[m=(b,np)][kk=jk*256+l] fp16 — transposed x stage, vectorized.
// ---------------------------------------------------------------------------
#define XP 520

__global__ void prep_a(const float* __restrict__ x) {
    extern __shared__ float xs[];  // [49][520]
    const int b = blockIdx.x;
    const float* xb = x + (size_t)b * CIN * HW;
    for (int i = threadIdx.x; i < CIN * HW; i += blockDim.x) {
        int c = i / HW, hw = i - c * HW;
        xs[hw * XP + c] = xb[i];
    }
    __syncthreads();

    __half* aout = Acol_g + (size_t)b * HW * KDIM;
    for (int idx = threadIdx.x; idx < HW * 9 * 32; idx += blockDim.x) {
        int l8 = idx & 31;
        int r  = idx >> 5;
        int jk = r % 9;
        int np = r / 9;
        int j = jk / 3, k = jk - 3 * j;
        int n = np / 7, p = np - 7 * n;

        int pk = p + k;
        bool pv = (pk >= 1 && pk <= 7);
        int w2 = (pk + 5) % 7;
        int ha = ((n + 6) % 7) + j - 1;
        int hb = n + j - 1;
        bool av = pv && (ha >= 0) && (ha < 7);
        bool bv = pv && (hb >= 0) && (hb < 7);

        int l0 = l8 * 8;
        float4 a0 = {0,0,0,0}, a1 = {0,0,0,0}, b0 = {0,0,0,0}, b1 = {0,0,0,0};
        if (av) {
            const float4* pa = (const float4*)(xs + (ha * 7 + w2) * XP + 256 + l0);
            a0 = pa[0]; a1 = pa[1];
        }
        if (bv) {
            const float4* pb = (const float4*)(xs + (hb * 7 + w2) * XP + l0);
            b0 = pb[0]; b1 = pb[1];
        }
        __half2 p0 = __floats2half2_rn(a0.x + b0.x, a0.y + b0.y);
        __half2 p1 = __floats2half2_rn(a0.z + b0.z, a0.w + b0.w);
        __half2 p2 = __floats2half2_rn(a1.x + b1.x, a1.y + b1.y);
        __half2 p3 = __floats2half2_rn(a1.z + b1.z, a1.w + b1.w);
        uint4 o;
        o.x = *reinterpret_cast<uint32_t*>(&p0);
        o.y = *reinterpret_cast<uint32_t*>(&p1);
        o.z = *reinterpret_cast<uint32_t*>(&p2);
        o.w = *reinterpret_cast<uint32_t*>(&p3);
        reinterpret_cast<uint4*>(aout)[np * (KDIM / 8) + jk * 32 + l8] = o;
    }
}

// ---------------------------------------------------------------------------
// Phase 1b: Whn[i][kk=jk*256+l] = fp16( W[l][j][k][i] )   (K-major per row)
// ---------------------------------------------------------------------------
__global__ void prep_w(const float* __restrict__ W) {
    int t = blockIdx.x * blockDim.x + threadIdx.x;  // over 512 * 1152 half2
    if (t >= NDIM * (KDIM / 2)) return;
    int i   = t / (KDIM / 2);
    int kk2 = t - i * (KDIM / 2);
    int kk  = kk2 * 2;
    int jk  = kk >> 8;
    int l   = kk & 255;
    float v0 = W[(size_t)(l * 9 + jk) * NDIM + i];
    float v1 = W[(size_t)((l + 1) * 9 + jk) * NDIM + i];
    reinterpret_cast<__half2*>(Whn_g)[t] = __floats2half2_rn(v0, v1);
}

// ---------------------------------------------------------------------------
// Phase 2: GEMM out[m][i] = sum_k A[m][k] * Whn[i][k]
// mma.sync m16n8k16, BM=128 BN=128 BK=64, 3-stage cp.async, SW128 smem.
// 8 warps (2x4), warp tile 64x32. Grid (4 bn, 392 bm) — B L2-resident,
// same-bm CTAs adjacent so A tiles hit L2.
// ---------------------------------------------------------------------------
#define BK 64
#define NC (KDIM / BK)        // 36
#define STG_H 8192            // halfs per stage per operand (128 * 64)
#define DSMEM (3 * 2 * STG_H * 2 + 256)

__device__ __forceinline__ void load_stage(
    const __half* __restrict__ Ag, const __half* __restrict__ Bg,
    uint32_t sA, uint32_t sB, int k0, int tid)
{
#pragma unroll
    for (int q = 0; q < 4; q++) {            // A: 128 rows x 4 chunks... 1024 x 16B
        int id = tid + q * 256;
        int r = id >> 3, c = id & 7;
        cpa16(sA + swz((uint32_t)(r * 128 + c * 16)),
              Ag + (size_t)r * KDIM + k0 + c * 8);
    }
#pragma unroll
    for (int q = 0; q < 4; q++) {            // B: 128 rows x 8 chunks of 16B
        int id = tid + q * 256;
        int r = id >> 3, c = id & 7;
        cpa16(sB + swz((uint32_t)(r * 128 + c * 16)),
              Bg + (size_t)r * KDIM + k0 + c * 8);
    }
    asm volatile("cp.async.commit_group;" ::: "memory");
}

__global__ __launch_bounds__(256, 2) void gemm_f16(float* __restrict__ out) {
    extern __shared__ char dsm[];
    const uint32_t sbase = (s2u(dsm) + 127) & ~127u;

    const int bn   = blockIdx.x;     // 0..3
    const int bm   = blockIdx.y;     // 0..391
    const int tid  = threadIdx.x;
    const int wid  = tid >> 5;
    const int lane = tid & 31;
    const int wm   = wid >> 2;       // 0..1
    const int wn   = wid & 3;        // 0..3

    const __half* Ag = Acol_g + (size_t)bm * 128 * KDIM;
    const __half* Bg = Whn_g + (size_t)bn * 128 * KDIM;

    // stage s: A at sbase + s*16384, B at sbase + 3*16384 + s*16384 (bytes)
    uint32_t sA[3], sB[3];
#pragma unroll
    for (int s = 0; s < 3; s++) {
        sA[s] = sbase + s * (STG_H * 2);
        sB[s] = sbase + (3 + s) * (STG_H * 2);
    }

    float acc[4][4][4];
#pragma unroll
    for (int a = 0; a < 4; a++)
#pragma unroll
        for (int b = 0; b < 4; b++)
#pragma unroll
            for (int c = 0; c < 4; c++) acc[a][b][c] = 0.f;

    load_stage(Ag, Bg, sA[0], sB[0], 0, tid);
    load_stage(Ag, Bg, sA[1], sB[1], BK, tid);

    // precomputed ldmatrix lane addressing (stage-relative byte offsets)
    const uint32_t a_off = swz((uint32_t)((wm * 64 + (lane & 15)) * 128 + (lane >> 4) * 16));
    const uint32_t b_off = swz((uint32_t)((wn * 32 + (lane & 7)) * 128 + ((lane >> 3) & 1) * 16));

    for (int t = 0; t < NC; t++) {
        if (t == NC - 1) asm volatile("cp.async.wait_group 0;" ::: "memory");
        else             asm volatile("cp.async.wait_group 1;" ::: "memory");
        __syncthreads();

        if (t + 2 < NC)
            load_stage(Ag, Bg, sA[(t + 2) % 3], sB[(t + 2) % 3], (t + 2) * BK, tid);

        const uint32_t cA = sA[t % 3];
        const uint32_t cB = sB[t % 3];
#pragma unroll
        for (int ks = 0; ks < 4; ks++) {
            const uint32_t kboff = ks * 32;  // 16 halfs = 32 B; swizzle-invariant add? no:
            // column shifts must go through swz; recompute per kstep:
            uint32_t a[4][4];
#pragma unroll
            for (int mi = 0; mi < 4; mi++) {
                uint32_t addr = cA + (a_off ^ swz((uint32_t)(mi * 16 * 128)) )
                                   + 0;  // rows add swizzle-invariant (multiple of 1024)
                addr = cA + ((a_off + mi * 16 * 128) );  // mi*2048 doesn't affect swz bits
                addr ^= 0;  // keep simple below
                uint32_t full = cA + swz((uint32_t)((wm * 64 + mi * 16 + (lane & 15)) * 128
                                                    + kboff + (lane >> 4) * 16));
                asm volatile("ldmatrix.sync.aligned.m8n8.x4.shared.b16 {%0,%1,%2,%3}, [%4];"
                             : "=r"(a[mi][0]), "=r"(a[mi][1]), "=r"(a[mi][2]), "=r"(a[mi][3])
                             : "r"(full));
                (void)addr;
            }
            uint32_t bf[4][2];
#pragma unroll
            for (int ni = 0; ni < 4; ni++) {
                uint32_t full = cB + swz((uint32_t)((wn * 32 + ni * 8 + (lane & 7)) * 128
                                                    + kboff + ((lane >> 3) & 1) * 16));
                asm volatile("ldmatrix.sync.aligned.m8n8.x2.shared.b16 {%0,%1}, [%2];"
                             : "=r"(bf[ni][0]), "=r"(bf[ni][1])
                             : "r"(full));
            }
#pragma unroll
            for (int mi = 0; mi < 4; mi++)
#pragma unroll
                for (int ni = 0; ni < 4; ni++) {
                    asm volatile(
                        "mma.sync.aligned.m16n8k16.row.col.f32.f16.f16.f32 "
                        "{%0,%1,%2,%3}, {%4,%5,%6,%7}, {%8,%9}, {%0,%1,%2,%3};"
                        : "+f"(acc[mi][ni][0]), "+f"(acc[mi][ni][1]),
                          "+f"(acc[mi][ni][2]), "+f"(acc[mi][ni][3])
                        : "r"(a[mi][0]), "r"(a[mi][1]), "r"(a[mi][2]), "r"(a[mi][3]),
                          "r"(bf[ni][0]), "r"(bf[ni][1]));
                }
        }
        __syncthreads();
    }

    // Epilogue: scatter to out[(b*512 + i)*49 + np]
    const int m_base = bm * 128 + wm * 64;
    const int i_base = bn * 128 + wn * 32;
#pragma unroll
    for (int mi = 0; mi < 4; mi++) {
#pragma unroll
        for (int ni = 0; ni < 4; ni++) {
            int row0 = m_base + mi * 16 + (lane >> 2);
            int col0 = i_base + ni * 8 + (lane & 3) * 2;
#pragma unroll
            for (int h = 0; h < 2; h++) {
                int m  = row0 + h * 8;
                int b  = m / 49;
                int np = m - b * 49;
                float* o = out + (size_t)(b * NDIM + col0) * 49 + np;
                o[0]  = acc[mi][ni][h * 2 + 0];
                o[49] = acc[mi][ni][h * 2 + 1];
            }
        }
    }
}

// ---------------------------------------------------------------------------
extern "C" void kernel_launch(void* const* d_in, const int* in_sizes, int n_in,
                              void* d_out, int out_size) {
    const float* x = (const float*)d_in[0];   // (1024, 512, 7, 7)
    const float* W = (const float*)d_in[1];   // (256, 3, 3, 512)
    float* out = (float*)d_out;               // (1024, 512, 7, 7)

    cudaFuncSetAttribute(prep_a, cudaFuncAttributeMaxDynamicSharedMemorySize,
                         HW * XP * (int)sizeof(float));
    cudaFuncSetAttribute(gemm_f16, cudaFuncAttributeMaxDynamicSharedMemorySize, DSMEM);

    prep_a<<<BATCH, 512, HW * XP * sizeof(float)>>>(x);
    prep_w<<<(NDIM * (KDIM / 2) + 255) / 256, 256>>>(W);
    gemm_f16<<<dim3(NDIM / 128, MDIM / 128), 256, DSMEM>>>(out);
}